// round 2
// baseline (speedup 1.0000x reference)
#include <cuda_runtime.h>
#include <math.h>

// Problem dims (fixed by the reference)
#define BB 128     // batch
#define TT 512     // time steps
#define DD 512     // input feature dim
#define UU 512     // GRU units
#define G3 1536    // 3*UU
#define NCTA 128   // persistent scan grid (must be <= SM count, 1 CTA/SM)

// ---------------------------------------------------------------------------
// Scratch (device globals — no allocations allowed)
// ---------------------------------------------------------------------------
__device__ float g_xproj[(size_t)TT * BB * G3];   // [t][b][3U]  (~402 MB)
__device__ float g_h0[BB * UU];
__device__ float g_h1[BB * UU];
__device__ float g_rh[BB * UU];

// Grid barrier state (zero-initialized at module load)
__device__ unsigned g_bar_count;
__device__ volatile unsigned g_bar_gen;

// Generation-based software grid barrier. Safe: all NCTA CTAs are co-resident
// (1 CTA/SM, NCTA <= SM count). Release: threadfence before arrive; acquire:
// threadfence after the generation flips.
__device__ __forceinline__ void grid_barrier()
{
    __syncthreads();
    if (threadIdx.x == 0) {
        __threadfence();
        unsigned gen = g_bar_gen;
        if (atomicAdd(&g_bar_count, 1u) == NCTA - 1) {
            g_bar_count = 0;
            __threadfence();
            g_bar_gen = gen + 1;
        } else {
            while (g_bar_gen == gen) { __nanosleep(32); }
        }
        __threadfence();
    }
    __syncthreads();
}

// ---------------------------------------------------------------------------
// Kernel 1: x_proj GEMM.  C[t][b][n] = sum_d inputs[b][t][d] * W[d][n] + bias[n]
// M = B*T = 65536 rows (m = b*T + t), K = 512, N = 1536.
// 128x128 tile, BK=16, 8x8 microtile, 256 threads.
// ---------------------------------------------------------------------------
__global__ __launch_bounds__(256) void xproj_gemm(
    const float* __restrict__ A,     // [B*T, D]
    const float* __restrict__ W,     // [D, 3U]
    const float* __restrict__ bias)  // [3U]
{
    __shared__ float As[16][132];    // transposed A tile, padded
    __shared__ float Bs[16][128];

    const int tid = threadIdx.x;
    const int m0  = blockIdx.y * 128;
    const int n0  = blockIdx.x * 128;
    const int tx  = tid & 15;        // n direction
    const int ty  = tid >> 4;        // m direction

    float acc[8][8];
#pragma unroll
    for (int i = 0; i < 8; i++)
#pragma unroll
        for (int j = 0; j < 8; j++) acc[i][j] = 0.f;

    for (int kc = 0; kc < DD; kc += 16) {
#pragma unroll
        for (int i = 0; i < 2; i++) {
            int id  = tid + i * 256;
            int row = id >> 2;
            int kq  = (id & 3) << 2;
            float4 v = *reinterpret_cast<const float4*>(
                &A[(size_t)(m0 + row) * DD + kc + kq]);
            As[kq + 0][row] = v.x;
            As[kq + 1][row] = v.y;
            As[kq + 2][row] = v.z;
            As[kq + 3][row] = v.w;

            int kr = id >> 5;
            int nq = (id & 31) << 2;
            float4 w = *reinterpret_cast<const float4*>(
                &W[(size_t)(kc + kr) * G3 + n0 + nq]);
            *reinterpret_cast<float4*>(&Bs[kr][nq]) = w;
        }
        __syncthreads();

#pragma unroll
        for (int k = 0; k < 16; k++) {
            float af[8], bf[8];
            *reinterpret_cast<float4*>(af)     = *reinterpret_cast<float4*>(&As[k][ty * 8]);
            *reinterpret_cast<float4*>(af + 4) = *reinterpret_cast<float4*>(&As[k][ty * 8 + 4]);
            *reinterpret_cast<float4*>(bf)     = *reinterpret_cast<float4*>(&Bs[k][tx * 8]);
            *reinterpret_cast<float4*>(bf + 4) = *reinterpret_cast<float4*>(&Bs[k][tx * 8 + 4]);
#pragma unroll
            for (int i = 0; i < 8; i++)
#pragma unroll
                for (int j = 0; j < 8; j++)
                    acc[i][j] = fmaf(af[i], bf[j], acc[i][j]);
        }
        __syncthreads();
    }

    float bv[8];
#pragma unroll
    for (int j = 0; j < 8; j++) bv[j] = bias[n0 + tx * 8 + j];

#pragma unroll
    for (int i = 0; i < 8; i++) {
        int m = m0 + ty * 8 + i;
        int b = m >> 9;          // m / 512
        int t = m & 511;
        float* dst = &g_xproj[((size_t)t * BB + b) * G3 + n0 + tx * 8];
        float4 o0, o1;
        o0.x = acc[i][0] + bv[0]; o0.y = acc[i][1] + bv[1];
        o0.z = acc[i][2] + bv[2]; o0.w = acc[i][3] + bv[3];
        o1.x = acc[i][4] + bv[4]; o1.y = acc[i][5] + bv[5];
        o1.z = acc[i][6] + bv[6]; o1.w = acc[i][7] + bv[7];
        *reinterpret_cast<float4*>(dst)     = o0;
        *reinterpret_cast<float4*>(dst + 4) = o1;
    }
}

// ---------------------------------------------------------------------------
// Kernel 2: persistent fused scan. One launch for all T=512 steps.
// Grid: 128 CTAs x 256 threads.  CTA (bx = cta&3, uy = cta>>2) owns the
// (32 b x 16 u) output tile.  R slices stay resident in SMEM for all steps.
//
// SMEM: Rs1[512][32] (Rz|Rr cols)  65536 B
//       Rs2[512][16] (Rh cols)     32768 B
//       hs [512][36] (h^T / rh^T staging, padded)  73728 B
//       red[32][32]  (k-slice reduction)            4096 B
//       total 176128 B
// ---------------------------------------------------------------------------
#define SCAN_SMEM ((512 * 32 + 512 * 16 + 512 * 36 + 32 * 32) * 4)

__global__ __launch_bounds__(256) void gru_scan(
    const float* __restrict__ R,     // [U, 3U]
    const float* __restrict__ attn,  // [B, T]
    float* __restrict__ out)         // [B, U]
{
    extern __shared__ float sm[];
    float* Rs1 = sm;                  // [512][32]
    float* Rs2 = Rs1 + 512 * 32;      // [512][16]
    float* hs  = Rs2 + 512 * 16;      // [512][36]
    float* red = hs + 512 * 36;       // [32][32]

    const int tid = threadIdx.x;
    const int cta = blockIdx.x;
    const int b0  = (cta & 3) * 32;
    const int u0  = (cta >> 2) * 16;

    // ---- Load R slices once (resident for the whole scan) ----
#pragma unroll
    for (int i = 0; i < 16; i++) {
        int id   = tid + i * 256;
        int k    = id >> 3;
        int seg  = id & 7;
        int gate = seg >> 2;          // 0 = z, 1 = r
        int q    = (seg & 3) << 2;
        float4 v = *reinterpret_cast<const float4*>(
            &R[(size_t)k * G3 + gate * UU + u0 + q]);
        *reinterpret_cast<float4*>(&Rs1[k * 32 + gate * 16 + q]) = v;
    }
#pragma unroll
    for (int i = 0; i < 8; i++) {
        int id = tid + i * 256;
        int k  = id >> 2;
        int q  = (id & 3) << 2;
        float4 v = *reinterpret_cast<const float4*>(
            &R[(size_t)k * G3 + 2 * UU + u0 + q]);
        *reinterpret_cast<float4*>(&Rs2[k * 16 + q]) = v;
    }

    // ---- h0 = 0 (each CTA zeroes its own tile) ----
#pragma unroll
    for (int i = 0; i < 2; i++) {
        int idx = tid + i * 256;
        int bb  = idx >> 4;
        int uu  = idx & 15;
        g_h0[(b0 + bb) * UU + u0 + uu] = 0.f;
    }
    grid_barrier();

    float* hin  = g_h0;
    float* hout = g_h1;

    const int bg  = tid & 7;          // 8 b-groups of 4
    const int cg1 = (tid >> 3) & 7;   // phase1: 8 c-groups of 4 (32 cols)
    const int ks1 = tid >> 6;         // phase1: 4 k-slices of 128
    const int cg2 = (tid >> 3) & 3;   // phase2: 4 c-groups of 4 (16 cols)
    const int ks2 = tid >> 5;         // phase2: 8 k-slices of 64

    for (int t = 0; t < TT; t++) {
        // ================= phase 1: Gz, Gr =================
        // stage h^T into hs[k][bb]
#pragma unroll
        for (int i = 0; i < 16; i++) {
            int id = tid + i * 256;
            int bb = id >> 7;
            int k4 = (id & 127) << 2;
            float4 v = *reinterpret_cast<const float4*>(&hin[(b0 + bb) * UU + k4]);
            hs[(k4 + 0) * 36 + bb] = v.x;
            hs[(k4 + 1) * 36 + bb] = v.y;
            hs[(k4 + 2) * 36 + bb] = v.z;
            hs[(k4 + 3) * 36 + bb] = v.w;
        }
        __syncthreads();

        float acc[4][4];
#pragma unroll
        for (int i = 0; i < 4; i++)
#pragma unroll
            for (int j = 0; j < 4; j++) acc[i][j] = 0.f;

        {
            const float* hp = hs  + (ks1 * 128) * 36 + bg * 4;
            const float* rp = Rs1 + (ks1 * 128) * 32 + cg1 * 4;
#pragma unroll 8
            for (int k = 0; k < 128; k++) {
                float4 a = *reinterpret_cast<const float4*>(hp);
                float4 w = *reinterpret_cast<const float4*>(rp);
                hp += 36; rp += 32;
                float av[4] = {a.x, a.y, a.z, a.w};
                float wv[4] = {w.x, w.y, w.z, w.w};
#pragma unroll
                for (int i = 0; i < 4; i++)
#pragma unroll
                    for (int j = 0; j < 4; j++)
                        acc[i][j] = fmaf(av[i], wv[j], acc[i][j]);
            }
        }
        // staged reduction across the 4 k-slices into red[32][32]
#pragma unroll 1
        for (int s = 0; s < 4; s++) {
            if (ks1 == s) {
#pragma unroll
                for (int i = 0; i < 4; i++)
#pragma unroll
                    for (int j = 0; j < 4; j++) {
                        float* p = &red[(bg * 4 + i) * 32 + cg1 * 4 + j];
                        if (s == 0) *p = acc[i][j];
                        else        *p += acc[i][j];
                    }
            }
            __syncthreads();
        }

        // epilogue: z, r; keep z and h_old in registers, write r*h globally
        float zreg[2], hreg[2];
#pragma unroll
        for (int i = 0; i < 2; i++) {
            int idx = tid + i * 256;
            int bb  = idx >> 4;
            int uu  = idx & 15;
            int b = b0 + bb, u = u0 + uu;
            const float* xp = &g_xproj[((size_t)t * BB + b) * G3];
            float Gz = red[bb * 32 + uu];
            float Gr = red[bb * 32 + 16 + uu];
            float z = fminf(fmaxf(0.2f * (xp[u] + Gz) + 0.5f, 0.f), 1.f);
            float r = fminf(fmaxf(0.2f * (xp[UU + u] + Gr) + 0.5f, 0.f), 1.f);
            float hold = hin[b * UU + u];
            zreg[i] = z;
            hreg[i] = hold;
            g_rh[b * UU + u] = r * hold;
        }
        grid_barrier();   // all rh written

        // ================= phase 2: Gh, state update =================
        // stage rh^T into hs[k][bb]
#pragma unroll
        for (int i = 0; i < 16; i++) {
            int id = tid + i * 256;
            int bb = id >> 7;
            int k4 = (id & 127) << 2;
            float4 v = *reinterpret_cast<const float4*>(&g_rh[(b0 + bb) * UU + k4]);
            hs[(k4 + 0) * 36 + bb] = v.x;
            hs[(k4 + 1) * 36 + bb] = v.y;
            hs[(k4 + 2) * 36 + bb] = v.z;
            hs[(k4 + 3) * 36 + bb] = v.w;
        }
        __syncthreads();

#pragma unroll
        for (int i = 0; i < 4; i++)
#pragma unroll
            for (int j = 0; j < 4; j++) acc[i][j] = 0.f;

        {
            const float* hp = hs  + (ks2 * 64) * 36 + bg * 4;
            const float* rp = Rs2 + (ks2 * 64) * 16 + cg2 * 4;
#pragma unroll 8
            for (int k = 0; k < 64; k++) {
                float4 a = *reinterpret_cast<const float4*>(hp);
                float4 w = *reinterpret_cast<const float4*>(rp);
                hp += 36; rp += 16;
                float av[4] = {a.x, a.y, a.z, a.w};
                float wv[4] = {w.x, w.y, w.z, w.w};
#pragma unroll
                for (int i = 0; i < 4; i++)
#pragma unroll
                    for (int j = 0; j < 4; j++)
                        acc[i][j] = fmaf(av[i], wv[j], acc[i][j]);
            }
        }
#pragma unroll 1
        for (int s = 0; s < 8; s++) {
            if (ks2 == s) {
#pragma unroll
                for (int i = 0; i < 4; i++)
#pragma unroll
                    for (int j = 0; j < 4; j++) {
                        float* p = &red[(bg * 4 + i) * 16 + cg2 * 4 + j];
                        if (s == 0) *p = acc[i][j];
                        else        *p += acc[i][j];
                    }
            }
            __syncthreads();
        }

        // epilogue: hh, h_new, attn blend
#pragma unroll
        for (int i = 0; i < 2; i++) {
            int idx = tid + i * 256;
            int bb  = idx >> 4;
            int uu  = idx & 15;
            int b = b0 + bb, u = u0 + uu;
            const float* xp = &g_xproj[((size_t)t * BB + b) * G3];
            float Gh = red[bb * 16 + uu];
            float hh = tanhf(xp[2 * UU + u] + Gh);
            float z = zreg[i], hold = hreg[i];
            float a = attn[b * TT + t];
            float hn = z * hold + (1.f - z) * hh;
            float ho = a * hn + (1.f - a) * hold;
            if (t == TT - 1) out[b * UU + u] = ho;
            else             hout[b * UU + u] = ho;
        }
        grid_barrier();   // all h written before next step reads it

        float* tmp = hin; hin = hout; hout = tmp;
    }
}

// ---------------------------------------------------------------------------
// Host launcher: exactly 2 kernel nodes (graph-capturable, tiny graph)
// ---------------------------------------------------------------------------
extern "C" void kernel_launch(void* const* d_in, const int* in_sizes, int n_in,
                              void* d_out, int out_size)
{
    (void)in_sizes; (void)n_in; (void)out_size;
    const float* inputs = (const float*)d_in[0];  // [B,T,D]
    const float* attn   = (const float*)d_in[1];  // [B,T,1]
    const float* W      = (const float*)d_in[2];  // [D,3U]
    const float* R      = (const float*)d_in[3];  // [U,3U]
    const float* bias   = (const float*)d_in[4];  // [3U]
    float* out = (float*)d_out;                   // [B,U]

    static int smem_set = 0;
    if (!smem_set) {
        cudaFuncSetAttribute(gru_scan, cudaFuncAttributeMaxDynamicSharedMemorySize, SCAN_SMEM);
        smem_set = 1;
    }

    dim3 ggrid(G3 / 128, (BB * TT) / 128);
    xproj_gemm<<<ggrid, 256>>>(inputs, W, bias);

    gru_scan<<<NCTA, 256, SCAN_SMEM>>>(R, attn, out);
}

// round 4
// speedup vs baseline: 1.6080x; 1.6080x over previous
#include <cuda_runtime.h>
#include <math.h>

// Problem dims (fixed by the reference)
#define BB 128     // batch
#define TT 512     // time steps
#define DD 512     // input feature dim
#define UU 512     // GRU units
#define G3 1536    // 3*UU
#define NCTA 128   // persistent scan grid (1 CTA/SM, co-resident)

// ---------------------------------------------------------------------------
// Scratch (device globals — no allocations allowed)
// ---------------------------------------------------------------------------
__device__ float g_xproj[(size_t)TT * BB * G3];   // [t][b][3U]
__device__ float g_h0[BB * UU];
__device__ float g_h1[BB * UU];
__device__ float g_rh[BB * UU];

// Grid barrier state (zero-initialized at module load)
__device__ unsigned g_bar_count;
__device__ volatile unsigned g_bar_gen;

__device__ __forceinline__ void grid_barrier()
{
    __syncthreads();
    if (threadIdx.x == 0) {
        __threadfence();
        unsigned gen = g_bar_gen;
        if (atomicAdd(&g_bar_count, 1u) == NCTA - 1) {
            g_bar_count = 0;
            __threadfence();
            g_bar_gen = gen + 1;
        } else {
            while (g_bar_gen == gen) { __nanosleep(32); }
        }
        __threadfence();
    }
    __syncthreads();
}

// Packed dual-FMA (Blackwell f32x2 pipe; 2x the scalar FFMA ceiling)
#define FFMA2(acc, a, b) \
    asm("fma.rn.f32x2 %0, %1, %2, %0;" : "+l"(acc) : "l"(a), "l"(b))

// Duplicate one fp32 into both halves of a 64-bit packed operand
#define DUP2(out, x) \
    asm("mov.b64 %0, {%1, %1};" : "=l"(out) : "r"(__float_as_uint(x)))

__device__ __forceinline__ float pair_sum(unsigned long long v)
{
    float lo = __uint_as_float((unsigned)(v & 0xffffffffull));
    float hi = __uint_as_float((unsigned)(v >> 32));
    return lo + hi;
}

// XOR swizzle of 16B quads within a 512-float row: quad q of row r lives at
// phys quad (q & ~7) | ((q&7) ^ (r>>2 & 7)).  Makes 8 consecutive 4-row groups
// hit disjoint bank quads for fixed q -> conflict-free LDS.128.
#define SWQ(row, q) (((q) & ~7) | (((q) & 7) ^ (((row) >> 2) & 7)))

typedef unsigned long long ull;

// ---------------------------------------------------------------------------
// Kernel 1: x_proj GEMM with f32x2 packed math.
// C[t][b][n] = sum_d inputs[b][t][d] * W[d][n] + bias[n]
// M = B*T = 65536 (m = b*T + t), K = 512, N = 1536.
// 128x128 tile, BK=16, 8x8 microtile (pairs along n), 256 threads.
// ---------------------------------------------------------------------------
__global__ __launch_bounds__(256) void xproj_gemm(
    const float* __restrict__ A,     // [B*T, D]
    const float* __restrict__ W,     // [D, 3U]
    const float* __restrict__ bias)  // [3U]
{
    __shared__ float As[16][132];
    __shared__ __align__(16) float Bs[16][128];

    const int tid = threadIdx.x;
    const int m0  = blockIdx.y * 128;
    const int n0  = blockIdx.x * 128;
    const int tx  = tid & 15;
    const int ty  = tid >> 4;

    ull accp[8][4];
#pragma unroll
    for (int i = 0; i < 8; i++)
#pragma unroll
        for (int j = 0; j < 4; j++) accp[i][j] = 0ull;

    for (int kc = 0; kc < DD; kc += 16) {
#pragma unroll
        for (int i = 0; i < 2; i++) {
            int id  = tid + i * 256;
            int row = id >> 2;
            int kq  = (id & 3) << 2;
            float4 v = *reinterpret_cast<const float4*>(
                &A[(size_t)(m0 + row) * DD + kc + kq]);
            As[kq + 0][row] = v.x;
            As[kq + 1][row] = v.y;
            As[kq + 2][row] = v.z;
            As[kq + 3][row] = v.w;

            int kr = id >> 5;
            int nq = (id & 31) << 2;
            float4 w = *reinterpret_cast<const float4*>(
                &W[(size_t)(kc + kr) * G3 + n0 + nq]);
            *reinterpret_cast<float4*>(&Bs[kr][nq]) = w;
        }
        __syncthreads();

#pragma unroll
        for (int k = 0; k < 16; k++) {
            float af[8];
            *reinterpret_cast<float4*>(af)     = *reinterpret_cast<float4*>(&As[k][ty * 8]);
            *reinterpret_cast<float4*>(af + 4) = *reinterpret_cast<float4*>(&As[k][ty * 8 + 4]);
            ull bfp[4];
            {
                ulonglong2 B0 = *reinterpret_cast<ulonglong2*>(&Bs[k][tx * 8]);
                ulonglong2 B1 = *reinterpret_cast<ulonglong2*>(&Bs[k][tx * 8 + 4]);
                bfp[0] = B0.x; bfp[1] = B0.y; bfp[2] = B1.x; bfp[3] = B1.y;
            }
#pragma unroll
            for (int i = 0; i < 8; i++) {
                ull ad; DUP2(ad, af[i]);
#pragma unroll
                for (int j = 0; j < 4; j++)
                    FFMA2(accp[i][j], ad, bfp[j]);
            }
        }
        __syncthreads();
    }

    float bv[8];
#pragma unroll
    for (int j = 0; j < 8; j++) bv[j] = bias[n0 + tx * 8 + j];

#pragma unroll
    for (int i = 0; i < 8; i++) {
        int m = m0 + ty * 8 + i;
        int b = m >> 9;
        int t = m & 511;
        float* dst = &g_xproj[((size_t)t * BB + b) * G3 + n0 + tx * 8];
        float c[8];
#pragma unroll
        for (int j = 0; j < 4; j++) {
            c[2 * j]     = __uint_as_float((unsigned)(accp[i][j] & 0xffffffffull));
            c[2 * j + 1] = __uint_as_float((unsigned)(accp[i][j] >> 32));
        }
        float4 o0, o1;
        o0.x = c[0] + bv[0]; o0.y = c[1] + bv[1];
        o0.z = c[2] + bv[2]; o0.w = c[3] + bv[3];
        o1.x = c[4] + bv[4]; o1.y = c[5] + bv[5];
        o1.z = c[6] + bv[6]; o1.w = c[7] + bv[7];
        *reinterpret_cast<float4*>(dst)     = o0;
        *reinterpret_cast<float4*>(dst + 4) = o1;
    }
}

// ---------------------------------------------------------------------------
// Kernel 2: persistent fused scan, f32x2 packed math, K-paired accumulators.
// 128 CTAs x 512 threads.  CTA (cta&3 -> 32-batch slice, cta>>2 -> 16-unit
// slice).  R kept resident in SMEM transposed (u-major, k-contiguous).
//
// SMEM floats: hs 32*512 | Rt1 32*512 | Rt2 16*512 | red 9216  = 50176 f
// ---------------------------------------------------------------------------
#define HS_F   (32 * 512)
#define RT1_F  (32 * 512)
#define RT2_F  (16 * 512)
#define RED_F  9216                  // max(8*32*34, 16*32*18)
#define SCAN_SMEM ((HS_F + RT1_F + RT2_F + RED_F) * 4)

__global__ __launch_bounds__(512) void gru_scan(
    const float* __restrict__ R,     // [U, 3U]
    const float* __restrict__ attn,  // [B, T]
    float* __restrict__ out)         // [B, U]
{
    extern __shared__ float sm[];
    float* hs  = sm;                  // [32][512]  h / rh rows (swizzled quads)
    float* Rt1 = hs + HS_F;           // [32][512]  rows 0-15: Rz^T, 16-31: Rr^T
    float* Rt2 = Rt1 + RT1_F;         // [16][512]  Rh^T
    float* red = Rt2 + RT2_F;

    const int tid = threadIdx.x;
    const int cta = blockIdx.x;
    const int b0  = (cta & 3) * 32;
    const int u0  = (cta >> 2) * 16;

    // ---- One-time: transpose R slices into SMEM (resident all 512 steps) ----
#pragma unroll 1
    for (int i = 0; i < 32; i++) {
        int id  = tid + i * 512;
        int row = id >> 9;
        int k   = id & 511;
        int col = (row < 16) ? (u0 + row) : (UU + u0 + (row - 16));
        float v = R[(size_t)k * G3 + col];
        int q = k >> 2;
        Rt1[row * 512 + SWQ(row, q) * 4 + (k & 3)] = v;
    }
#pragma unroll 1
    for (int i = 0; i < 16; i++) {
        int id  = tid + i * 512;
        int row = id >> 9;
        int k   = id & 511;
        float v = R[(size_t)k * G3 + 2 * UU + u0 + row];
        int q = k >> 2;
        Rt2[row * 512 + SWQ(row, q) * 4 + (k & 3)] = v;
    }

    // ---- h0 = 0 ----
    {
        int bb = tid >> 4, uu = tid & 15;
        g_h0[(b0 + bb) * UU + u0 + uu] = 0.f;
    }
    grid_barrier();

    float* hin  = g_h0;
    float* hout = g_h1;

    const int bg  = tid & 7;              // 8 groups of 4 batch rows
    const int ug1 = (tid >> 3) & 7;       // phase1: 8 groups of 4 cols (of 32)
    const int ks1 = tid >> 6;             // phase1: 8 k-slices of 64
    const int ug2 = (tid >> 3) & 3;       // phase2: 4 groups of 4 cols (of 16)
    const int ks2 = tid >> 5;             // phase2: 16 k-slices of 32

    const int bb = tid >> 4;              // epilogue element mapping (1/thread)
    const int uu = tid & 15;
    const int b  = b0 + bb;
    const int u  = u0 + uu;
    const int hq    = u >> 2;
    const int holdx = bb * 512 + SWQ(bb, hq) * 4 + (u & 3);

    const float* hr1[4]; const float* wr1[4]; const float* wr2[4];
#pragma unroll
    for (int i = 0; i < 4; i++) hr1[i] = hs  + (bg  * 4 + i) * 512;
#pragma unroll
    for (int j = 0; j < 4; j++) wr1[j] = Rt1 + (ug1 * 4 + j) * 512;
#pragma unroll
    for (int j = 0; j < 4; j++) wr2[j] = Rt2 + (ug2 * 4 + j) * 512;

    for (int t = 0; t < TT; t++) {
        // ========== phase 1: Gz | Gr = h @ [Rz|Rr] ==========
#pragma unroll
        for (int i = 0; i < 8; i++) {
            int id  = tid + i * 512;
            int row = id >> 7;
            int q   = id & 127;
            float4 v = *reinterpret_cast<const float4*>(
                &hin[(b0 + row) * UU + q * 4]);
            *reinterpret_cast<float4*>(&hs[row * 512 + SWQ(row, q) * 4]) = v;
        }
        __syncthreads();

        ull acc[4][4];
#pragma unroll
        for (int i = 0; i < 4; i++)
#pragma unroll
            for (int j = 0; j < 4; j++) acc[i][j] = 0ull;

#pragma unroll 4
        for (int qq = 0; qq < 16; qq++) {
            int q  = ks1 * 16 + qq;
            int qa = ((q & ~7) | ((q & 7) ^ bg )) * 4;
            int qw = ((q & ~7) | ((q & 7) ^ ug1)) * 4;
            ull a0[4], a1[4], w0[4], w1[4];
#pragma unroll
            for (int i = 0; i < 4; i++) {
                ulonglong2 A = *reinterpret_cast<const ulonglong2*>(hr1[i] + qa);
                a0[i] = A.x; a1[i] = A.y;
            }
#pragma unroll
            for (int j = 0; j < 4; j++) {
                ulonglong2 Wv = *reinterpret_cast<const ulonglong2*>(wr1[j] + qw);
                w0[j] = Wv.x; w1[j] = Wv.y;
            }
#pragma unroll
            for (int i = 0; i < 4; i++)
#pragma unroll
                for (int j = 0; j < 4; j++) {
                    FFMA2(acc[i][j], a0[i], w0[j]);
                    FFMA2(acc[i][j], a1[i], w1[j]);
                }
        }

        // k-slice reduction: red1[8][32][34]
#pragma unroll
        for (int i = 0; i < 4; i++)
#pragma unroll
            for (int j2 = 0; j2 < 2; j2++) {
                float2 v;
                v.x = pair_sum(acc[i][2 * j2]);
                v.y = pair_sum(acc[i][2 * j2 + 1]);
                *reinterpret_cast<float2*>(
                    &red[ks1 * 1088 + (bg * 4 + i) * 34 + ug1 * 4 + 2 * j2]) = v;
            }
        __syncthreads();

        float gz = 0.f, gr = 0.f;
#pragma unroll
        for (int s = 0; s < 8; s++) {
            int base = s * 1088 + bb * 34;
            gz += red[base + uu];
            gr += red[base + 16 + uu];
        }

        const float* xp = &g_xproj[((size_t)t * BB + b) * G3];
        float z = fminf(fmaxf(0.2f * (xp[u] + gz) + 0.5f, 0.f), 1.f);
        float r = fminf(fmaxf(0.2f * (xp[UU + u] + gr) + 0.5f, 0.f), 1.f);
        float hold = hs[holdx];
        g_rh[b * UU + u] = r * hold;
        grid_barrier();   // all rh visible

        // ========== phase 2: Gh = (r*h) @ Rh ==========
#pragma unroll
        for (int i = 0; i < 8; i++) {
            int id  = tid + i * 512;
            int row = id >> 7;
            int q   = id & 127;
            float4 v = *reinterpret_cast<const float4*>(
                &g_rh[(b0 + row) * UU + q * 4]);
            *reinterpret_cast<float4*>(&hs[row * 512 + SWQ(row, q) * 4]) = v;
        }
        __syncthreads();

#pragma unroll
        for (int i = 0; i < 4; i++)
#pragma unroll
            for (int j = 0; j < 4; j++) acc[i][j] = 0ull;

#pragma unroll 4
        for (int qq = 0; qq < 8; qq++) {
            int q  = ks2 * 8 + qq;
            int qa = ((q & ~7) | ((q & 7) ^ bg )) * 4;
            int qw = ((q & ~7) | ((q & 7) ^ ug2)) * 4;
            ull a0[4], a1[4], w0[4], w1[4];
#pragma unroll
            for (int i = 0; i < 4; i++) {
                ulonglong2 A = *reinterpret_cast<const ulonglong2*>(hr1[i] + qa);
                a0[i] = A.x; a1[i] = A.y;
            }
#pragma unroll
            for (int j = 0; j < 4; j++) {
                ulonglong2 Wv = *reinterpret_cast<const ulonglong2*>(wr2[j] + qw);
                w0[j] = Wv.x; w1[j] = Wv.y;
            }
#pragma unroll
            for (int i = 0; i < 4; i++)
#pragma unroll
                for (int j = 0; j < 4; j++) {
                    FFMA2(acc[i][j], a0[i], w0[j]);
                    FFMA2(acc[i][j], a1[i], w1[j]);
                }
        }

        // reduction: red2[16][32][18]
#pragma unroll
        for (int i = 0; i < 4; i++)
#pragma unroll
            for (int j2 = 0; j2 < 2; j2++) {
                float2 v;
                v.x = pair_sum(acc[i][2 * j2]);
                v.y = pair_sum(acc[i][2 * j2 + 1]);
                *reinterpret_cast<float2*>(
                    &red[ks2 * 576 + (bg * 4 + i) * 18 + ug2 * 4 + 2 * j2]) = v;
            }
        __syncthreads();

        float gh = 0.f;
#pragma unroll
        for (int s = 0; s < 16; s++)
            gh += red[s * 576 + bb * 18 + uu];

        float hh = tanhf(xp[2 * UU + u] + gh);
        float a = attn[b * TT + t];
        float hn = z * hold + (1.f - z) * hh;
        float ho = a * hn + (1.f - a) * hold;
        if (t == TT - 1) out[b * UU + u] = ho;
        else             hout[b * UU + u] = ho;
        grid_barrier();   // all h written before next step reads it

        float* tmp = hin; hin = hout; hout = tmp;
    }
}

// ---------------------------------------------------------------------------
// Host launcher: 2 kernel nodes
// ---------------------------------------------------------------------------
extern "C" void kernel_launch(void* const* d_in, const int* in_sizes, int n_in,
                              void* d_out, int out_size)
{
    (void)in_sizes; (void)n_in; (void)out_size;
    const float* inputs = (const float*)d_in[0];  // [B,T,D]
    const float* attn   = (const float*)d_in[1];  // [B,T,1]
    const float* W      = (const float*)d_in[2];  // [D,3U]
    const float* R      = (const float*)d_in[3];  // [U,3U]
    const float* bias   = (const float*)d_in[4];  // [3U]
    float* out = (float*)d_out;                   // [B,U]

    static int smem_set = 0;
    if (!smem_set) {
        cudaFuncSetAttribute(gru_scan, cudaFuncAttributeMaxDynamicSharedMemorySize, SCAN_SMEM);
        smem_set = 1;
    }

    dim3 ggrid(G3 / 128, (BB * TT) / 128);
    xproj_gemm<<<ggrid, 256>>>(inputs, W, bias);

    gru_scan<<<NCTA, 512, SCAN_SMEM>>>(R, attn, out);
}

// round 5
// speedup vs baseline: 1.6531x; 1.0281x over previous
#include <cuda_runtime.h>
#include <math.h>

// Problem dims (fixed by the reference)
#define BB 128     // batch
#define TT 512     // time steps
#define DD 512     // input feature dim
#define UU 512     // GRU units
#define G3 1536    // 3*UU
#define NCTA 128   // persistent scan grid (1 CTA/SM, co-resident)

// ---------------------------------------------------------------------------
// Scratch (device globals — no allocations allowed)
// ---------------------------------------------------------------------------
__device__ float g_xproj[(size_t)TT * BB * G3];   // [t][b][3U]
__device__ float g_h0[BB * UU];
__device__ float g_h1[BB * UU];
__device__ float g_rh[BB * UU];

// Grid barrier state (zero-initialized at module load)
__device__ unsigned g_bar_count;
__device__ volatile unsigned g_bar_gen;

__device__ __forceinline__ void grid_barrier()
{
    __syncthreads();
    if (threadIdx.x == 0) {
        __threadfence();
        unsigned gen = g_bar_gen;
        if (atomicAdd(&g_bar_count, 1u) == NCTA - 1) {
            g_bar_count = 0;
            __threadfence();
            g_bar_gen = gen + 1;
        } else {
            while (g_bar_gen == gen) { __nanosleep(32); }
        }
        __threadfence();
    }
    __syncthreads();
}

typedef unsigned long long ull;

// Packed dual-FMA / dual-ADD (Blackwell f32x2 pipe)
#define FFMA2(acc, a, b) \
    asm("fma.rn.f32x2 %0, %1, %2, %0;" : "+l"(acc) : "l"(a), "l"(b))
#define ADD2(out, x, y) \
    asm("add.rn.f32x2 %0, %1, %2;" : "=l"(out) : "l"(x), "l"(y))
#define DUP2(out, x) \
    asm("mov.b64 %0, {%1, %1};" : "=l"(out) : "r"(__float_as_uint(x)))

__device__ __forceinline__ ull pack2(float lo, float hi)
{
    ull r;
    asm("mov.b64 %0, {%1, %2};" : "=l"(r)
        : "r"(__float_as_uint(lo)), "r"(__float_as_uint(hi)));
    return r;
}

// ---------------------------------------------------------------------------
// Kernel 1: x_proj GEMM with f32x2 packed math (unchanged from R4).
// ---------------------------------------------------------------------------
__global__ __launch_bounds__(256) void xproj_gemm(
    const float* __restrict__ A,     // [B*T, D]
    const float* __restrict__ W,     // [D, 3U]
    const float* __restrict__ bias)  // [3U]
{
    __shared__ float As[16][132];
    __shared__ __align__(16) float Bs[16][128];

    const int tid = threadIdx.x;
    const int m0  = blockIdx.y * 128;
    const int n0  = blockIdx.x * 128;
    const int tx  = tid & 15;
    const int ty  = tid >> 4;

    ull accp[8][4];
#pragma unroll
    for (int i = 0; i < 8; i++)
#pragma unroll
        for (int j = 0; j < 4; j++) accp[i][j] = 0ull;

    for (int kc = 0; kc < DD; kc += 16) {
#pragma unroll
        for (int i = 0; i < 2; i++) {
            int id  = tid + i * 256;
            int row = id >> 2;
            int kq  = (id & 3) << 2;
            float4 v = *reinterpret_cast<const float4*>(
                &A[(size_t)(m0 + row) * DD + kc + kq]);
            As[kq + 0][row] = v.x;
            As[kq + 1][row] = v.y;
            As[kq + 2][row] = v.z;
            As[kq + 3][row] = v.w;

            int kr = id >> 5;
            int nq = (id & 31) << 2;
            float4 w = *reinterpret_cast<const float4*>(
                &W[(size_t)(kc + kr) * G3 + n0 + nq]);
            *reinterpret_cast<float4*>(&Bs[kr][nq]) = w;
        }
        __syncthreads();

#pragma unroll
        for (int k = 0; k < 16; k++) {
            float af[8];
            *reinterpret_cast<float4*>(af)     = *reinterpret_cast<float4*>(&As[k][ty * 8]);
            *reinterpret_cast<float4*>(af + 4) = *reinterpret_cast<float4*>(&As[k][ty * 8 + 4]);
            ull bfp[4];
            {
                ulonglong2 B0 = *reinterpret_cast<ulonglong2*>(&Bs[k][tx * 8]);
                ulonglong2 B1 = *reinterpret_cast<ulonglong2*>(&Bs[k][tx * 8 + 4]);
                bfp[0] = B0.x; bfp[1] = B0.y; bfp[2] = B1.x; bfp[3] = B1.y;
            }
#pragma unroll
            for (int i = 0; i < 8; i++) {
                ull ad; DUP2(ad, af[i]);
#pragma unroll
                for (int j = 0; j < 4; j++)
                    FFMA2(accp[i][j], ad, bfp[j]);
            }
        }
        __syncthreads();
    }

    float bv[8];
#pragma unroll
    for (int j = 0; j < 8; j++) bv[j] = bias[n0 + tx * 8 + j];

#pragma unroll
    for (int i = 0; i < 8; i++) {
        int m = m0 + ty * 8 + i;
        int b = m >> 9;
        int t = m & 511;
        float* dst = &g_xproj[((size_t)t * BB + b) * G3 + n0 + tx * 8];
        float c[8];
#pragma unroll
        for (int j = 0; j < 4; j++) {
            c[2 * j]     = __uint_as_float((unsigned)(accp[i][j] & 0xffffffffull));
            c[2 * j + 1] = __uint_as_float((unsigned)(accp[i][j] >> 32));
        }
        float4 o0, o1;
        o0.x = c[0] + bv[0]; o0.y = c[1] + bv[1];
        o0.z = c[2] + bv[2]; o0.w = c[3] + bv[3];
        o1.x = c[4] + bv[4]; o1.y = c[5] + bv[5];
        o1.z = c[6] + bv[6]; o1.w = c[7] + bv[7];
        *reinterpret_cast<float4*>(dst)     = o0;
        *reinterpret_cast<float4*>(dst + 4) = o1;
    }
}

// ---------------------------------------------------------------------------
// Kernel 2: persistent fused scan.  128 CTAs x 512 threads (16 warps).
// CTA tile: 32 batch x 16 units.  Warp-owned 8x8 output microtiles with
// k spread over lanes (k = 32*j + lane); in-register butterfly reduction.
//
// SMEM (bytes):
//   hs    [32][512] f                65536
//   Rt1p  [512][17] ull (16 used)    69632   (z-pairs p<8, r-pairs p>=8)
//   Rt2p  [512][9]  ull (8 used)     36864
//   gbuf  [32][17]  ull (16 used)     4352
//   ghbuf [2][8][32] ull              4096
//   total                           180480
// ---------------------------------------------------------------------------
#define HS_F      (32 * 512)
#define RT1P_U    (512 * 17)
#define RT2P_U    (512 * 9)
#define GBUF_U    (32 * 17)
#define GHBUF_U   (2 * 8 * 32)
#define SCAN_SMEM (HS_F * 4 + (RT1P_U + RT2P_U + GBUF_U + GHBUF_U) * 8)

__global__ __launch_bounds__(512) void gru_scan(
    const float* __restrict__ R,     // [U, 3U]
    const float* __restrict__ attn,  // [B, T]
    float* __restrict__ out)         // [B, U]
{
    extern __shared__ float sm[];
    float* hs   = sm;
    ull* Rt1p   = reinterpret_cast<ull*>(sm + HS_F);
    ull* Rt2p   = Rt1p + RT1P_U;
    ull* gbuf   = Rt2p + RT2P_U;
    ull* ghbuf  = gbuf + GBUF_U;

    const int tid  = threadIdx.x;
    const int cta  = blockIdx.x;
    const int b0   = (cta & 3) * 32;
    const int u0   = (cta >> 2) * 16;
    const int warp = tid >> 5;
    const int lane = tid & 31;

    // ---- One-time: pack R slices into SMEM pair layouts ----
    {
        int k = tid;  // 512 threads, one k each
#pragma unroll
        for (int p = 0; p < 16; p++) {
            int col = (p < 8) ? (u0 + 2 * p) : (UU + u0 + 2 * (p - 8));
            const float* rp = &R[(size_t)k * G3 + col];
            Rt1p[k * 17 + p] = pack2(rp[0], rp[1]);
        }
#pragma unroll
        for (int p = 0; p < 8; p++) {
            const float* rp = &R[(size_t)k * G3 + 2 * UU + u0 + 2 * p];
            Rt2p[k * 9 + p] = pack2(rp[0], rp[1]);
        }
    }

    // ---- h0 = 0 ----
    {
        int eb = tid >> 4, eu = tid & 15;
        g_h0[(b0 + eb) * UU + u0 + eu] = 0.f;
    }
    grid_barrier();

    float* hin  = g_h0;
    float* hout = g_h1;

    // phase1 warp tile ids: 4 b-blocks x 4 u-blocks of 8
    const int bw  = warp & 3;
    const int uw  = warp >> 2;
    // phase2: 4 b-blocks x 2 u-blocks x 2 k-halves
    const int bw2 = warp & 3;
    const int uw2 = (warp >> 2) & 1;
    const int kh  = warp >> 3;
    // epilogue mapping: one (b,u) element per thread
    const int eb = tid >> 4;
    const int eu = tid & 15;
    const int gb = b0 + eb;
    const int gu = u0 + eu;

    for (int t = 0; t < TT; t++) {
        // ---- stage h rows into hs [32][512] ----
#pragma unroll
        for (int i = 0; i < 8; i++) {
            int id  = tid + i * 512;
            int row = id >> 7;
            int q   = id & 127;
            *reinterpret_cast<float4*>(&hs[row * 512 + q * 4]) =
                *reinterpret_cast<const float4*>(&hin[(b0 + row) * UU + q * 4]);
        }
        __syncthreads();

        // ======== phase 1: [32b x 512k] @ [512k x 32c]  (c = z|r) ========
        ull acc[8][4];
#pragma unroll
        for (int i = 0; i < 8; i++)
#pragma unroll
            for (int p = 0; p < 4; p++) acc[i][p] = 0ull;

        {
            const float* ap = hs + (bw * 8) * 512 + lane;
            const ull*   wp = Rt1p + lane * 17 + uw * 4;
#pragma unroll 4
            for (int j = 0; j < 16; j++) {
                ull w[4];
#pragma unroll
                for (int p = 0; p < 4; p++) w[p] = wp[p];
                wp += 32 * 17;
#pragma unroll
                for (int i = 0; i < 8; i++) {
                    float a = ap[i * 512 + j * 32];
                    ull ad; DUP2(ad, a);
#pragma unroll
                    for (int p = 0; p < 4; p++)
                        FFMA2(acc[i][p], ad, w[p]);
                }
            }
        }

        // butterfly reduction over lanes (k-slices); lane l ends owning flat idx l
        {
            ull* v = &acc[0][0];
#pragma unroll
            for (int d = 16; d >= 1; d >>= 1) {
                bool hi = (lane & d) != 0;
#pragma unroll
                for (int i = 0; i < 32; i++) {
                    if (i >= d) break;   // only first `d` entries active
                    ull send = hi ? v[i] : v[i + d];
                    ull recv = __shfl_xor_sync(0xffffffffu, send, d);
                    ull keep = hi ? v[i + d] : v[i];
                    ADD2(v[i], keep, recv);
                }
            }
            // write my output pair to gbuf: row = bw*8 + lane>>2, pair col = uw*4 + (lane&3)
            gbuf[(bw * 8 + (lane >> 2)) * 17 + uw * 4 + (lane & 3)] = v[0];
        }
        __syncthreads();

        // ---- epilogue 1: z, r; write rh ----
        const float* gf = reinterpret_cast<const float*>(gbuf);  // row stride 34
        float gz = gf[eb * 34 + eu];
        float gr = gf[eb * 34 + 16 + eu];
        const float* xp = &g_xproj[((size_t)t * BB + gb) * G3];
        float z = fminf(fmaxf(0.2f * (xp[gu] + gz) + 0.5f, 0.f), 1.f);
        float r = fminf(fmaxf(0.2f * (xp[UU + gu] + gr) + 0.5f, 0.f), 1.f);
        float hold = hs[eb * 512 + gu];
        g_rh[gb * UU + gu] = r * hold;
        grid_barrier();   // all rh visible

        // ---- stage rh into hs ----
#pragma unroll
        for (int i = 0; i < 8; i++) {
            int id  = tid + i * 512;
            int row = id >> 7;
            int q   = id & 127;
            *reinterpret_cast<float4*>(&hs[row * 512 + q * 4]) =
                *reinterpret_cast<const float4*>(&g_rh[(b0 + row) * UU + q * 4]);
        }
        __syncthreads();

        // ======== phase 2: [32b x 512k] @ [512k x 16u], k split 2 ways ========
        ull acc2[8][4];
#pragma unroll
        for (int i = 0; i < 8; i++)
#pragma unroll
            for (int p = 0; p < 4; p++) acc2[i][p] = 0ull;

        {
            const float* ap = hs + (bw2 * 8) * 512 + kh * 256 + lane;
            const ull*   wp = Rt2p + (kh * 256 + lane) * 9 + uw2 * 4;
#pragma unroll 4
            for (int j = 0; j < 8; j++) {
                ull w[4];
#pragma unroll
                for (int p = 0; p < 4; p++) w[p] = wp[p];
                wp += 32 * 9;
#pragma unroll
                for (int i = 0; i < 8; i++) {
                    float a = ap[i * 512 + j * 32];
                    ull ad; DUP2(ad, a);
#pragma unroll
                    for (int p = 0; p < 4; p++)
                        FFMA2(acc2[i][p], ad, w[p]);
                }
            }
        }

        {
            ull* v = &acc2[0][0];
#pragma unroll
            for (int d = 16; d >= 1; d >>= 1) {
                bool hi = (lane & d) != 0;
#pragma unroll
                for (int i = 0; i < 32; i++) {
                    if (i >= d) break;
                    ull send = hi ? v[i] : v[i + d];
                    ull recv = __shfl_xor_sync(0xffffffffu, send, d);
                    ull keep = hi ? v[i + d] : v[i];
                    ADD2(v[i], keep, recv);
                }
            }
            int tile = uw2 * 4 + bw2;
            ghbuf[kh * 256 + tile * 32 + lane] = v[0];
        }
        __syncthreads();

        // ---- epilogue 2: hh, state update, attn blend ----
        {
            int bt   = eb >> 3;
            int ut   = eu >> 3;
            int tile = ut * 4 + bt;
            int li   = (eb & 7) * 4 + ((eu >> 1) & 3);
            const float* ghf = reinterpret_cast<const float*>(ghbuf);
            float gh = ghf[(tile * 32 + li) * 2 + (eu & 1)]
                     + ghf[(256 + tile * 32 + li) * 2 + (eu & 1)];
            float hh = tanhf(xp[2 * UU + gu] + gh);
            float a  = attn[gb * TT + t];
            float hn = z * hold + (1.f - z) * hh;
            float ho = a * hn + (1.f - a) * hold;
            if (t == TT - 1) out[gb * UU + gu] = ho;
            else             hout[gb * UU + gu] = ho;
        }
        grid_barrier();   // all h written before next step reads it

        float* tmp = hin; hin = hout; hout = tmp;
    }
}

// ---------------------------------------------------------------------------
// Host launcher: 2 kernel nodes
// ---------------------------------------------------------------------------
extern "C" void kernel_launch(void* const* d_in, const int* in_sizes, int n_in,
                              void* d_out, int out_size)
{
    (void)in_sizes; (void)n_in; (void)out_size;
    const float* inputs = (const float*)d_in[0];  // [B,T,D]
    const float* attn   = (const float*)d_in[1];  // [B,T,1]
    const float* W      = (const float*)d_in[2];  // [D,3U]
    const float* R      = (const float*)d_in[3];  // [U,3U]
    const float* bias   = (const float*)d_in[4];  // [3U]
    float* out = (float*)d_out;                   // [B,U]

    static int smem_set = 0;
    if (!smem_set) {
        cudaFuncSetAttribute(gru_scan, cudaFuncAttributeMaxDynamicSharedMemorySize, SCAN_SMEM);
        smem_set = 1;
    }

    dim3 ggrid(G3 / 128, (BB * TT) / 128);
    xproj_gemm<<<ggrid, 256>>>(inputs, W, bias);

    gru_scan<<<NCTA, 512, SCAN_SMEM>>>(R, attn, out);
}